// round 6
// baseline (speedup 1.0000x reference)
#include <cuda_runtime.h>

#define DIM 128
#define DIM4 (DIM / 4)          // 32 float4 per row
#define NODES_MAX 50000
#define NRELS_MAX 1000
#define NSTATB 512              // partial-stat blocks (deterministic 2-level reduce)
#define BN_EPS 1e-5f

// Scratch (static device globals — allowed; no runtime allocation)
__device__ float g_xn[NODES_MAX * DIM];      // normalized x (read by edge gather)
__device__ float g_rsc[NRELS_MAX * DIM];     // r * kernels
__device__ float g_psum[NSTATB * DIM];       // partial column sums
__device__ float g_psq[NSTATB * DIM];        // partial column sum-of-squares
__device__ float g_ca[DIM];                  // fused scale
__device__ float g_cb[DIM];                  // fused shift

// ---------------------------------------------------------------------------
// K1: per-block partial column sums (coalesced: thread d reads column d)
// ---------------------------------------------------------------------------
__global__ void k_stats(const float* __restrict__ x, int e) {
    int d = threadIdx.x;            // 0..127
    int b = blockIdx.x;             // 0..NSTATB-1
    float s = 0.f, ss = 0.f;
    for (int row = b; row < e; row += NSTATB) {
        float v = x[(size_t)row * DIM + d];
        s += v;
        ss += v * v;
    }
    g_psum[b * DIM + d] = s;
    g_psq[b * DIM + d] = ss;
}

// ---------------------------------------------------------------------------
// K2: reduce partials (double accum), build fused affine coefficients
// ---------------------------------------------------------------------------
__global__ void k_coef(const float* __restrict__ gamma,
                       const float* __restrict__ beta,
                       const float* __restrict__ kern, int e) {
    int d = threadIdx.x;
    double s = 0.0, ss = 0.0;
    for (int b = 0; b < NSTATB; b++) {
        s += (double)g_psum[b * DIM + d];
        ss += (double)g_psq[b * DIM + d];
    }
    double mean_d = s / (double)e;
    double var_d  = ss / (double)e - mean_d * mean_d;   // biased variance
    float mean = (float)mean_d;
    float inv = rsqrtf((float)var_d + BN_EPS);
    float g = gamma[d], k = kern[d];
    g_ca[d] = inv * g * k;
    g_cb[d] = (beta[d] - mean * inv * g) * k;
}

// ---------------------------------------------------------------------------
// K3: r * kernels
// ---------------------------------------------------------------------------
__global__ void k_rsc(const float* __restrict__ r,
                      const float* __restrict__ kern, int total) {
    int i = blockIdx.x * blockDim.x + threadIdx.x;
    if (i < total) g_rsc[i] = r[i] * kern[i & (DIM - 1)];
}

// ---------------------------------------------------------------------------
// K4: xn = x*a + b ; write to scratch AND seed d_out (acc = xn + scatters)
// ---------------------------------------------------------------------------
__global__ void k_norm(const float* __restrict__ x, float* __restrict__ out,
                       int total4) {
    int i = blockIdx.x * blockDim.x + threadIdx.x;
    if (i >= total4) return;
    float4 v = reinterpret_cast<const float4*>(x)[i];
    int dg = i & (DIM4 - 1);
    float4 a = reinterpret_cast<const float4*>(g_ca)[dg];
    float4 b = reinterpret_cast<const float4*>(g_cb)[dg];
    float4 o;
    o.x = v.x * a.x + b.x;
    o.y = v.y * a.y + b.y;
    o.z = v.z * a.z + b.z;
    o.w = v.w * a.w + b.w;
    reinterpret_cast<float4*>(g_xn)[i] = o;
    reinterpret_cast<float4*>(out)[i] = o;
}

// ---------------------------------------------------------------------------
// K5: edge pass — one warp per edge, float4 per lane, vector red.global.add
//   out[tail] += xn[head] + rsc[rel]
//   out[head] += xn[tail] - rsc[rel]
// Indices are INT32 (JAX x64 disabled downgrades int64 -> int32).
// ---------------------------------------------------------------------------
__global__ void __launch_bounds__(256) k_edges(
        const int* __restrict__ heads,
        const int* __restrict__ tails,
        const int* __restrict__ rels,
        float* __restrict__ out, int E) {
    int w = (blockIdx.x * blockDim.x + threadIdx.x) >> 5;
    if (w >= E) return;
    int lane = threadIdx.x & 31;

    int h  = heads[w];
    int t  = tails[w];
    int rl = rels[w];

    float4 xh = __ldg(reinterpret_cast<const float4*>(g_xn + (size_t)h * DIM) + lane);
    float4 xt = __ldg(reinterpret_cast<const float4*>(g_xn + (size_t)t * DIM) + lane);
    float4 rr = __ldg(reinterpret_cast<const float4*>(g_rsc + (size_t)rl * DIM) + lane);

    float4 recv, send;
    recv.x = xh.x + rr.x; recv.y = xh.y + rr.y;
    recv.z = xh.z + rr.z; recv.w = xh.w + rr.w;
    send.x = xt.x - rr.x; send.y = xt.y - rr.y;
    send.z = xt.z - rr.z; send.w = xt.w - rr.w;

    float* dt = out + (size_t)t * DIM + lane * 4;
    float* dh = out + (size_t)h * DIM + lane * 4;
    asm volatile("red.global.add.v4.f32 [%0], {%1,%2,%3,%4};"
                 :: "l"(dt), "f"(recv.x), "f"(recv.y), "f"(recv.z), "f"(recv.w)
                 : "memory");
    asm volatile("red.global.add.v4.f32 [%0], {%1,%2,%3,%4};"
                 :: "l"(dh), "f"(send.x), "f"(send.y), "f"(send.z), "f"(send.w)
                 : "memory");
}

// ---------------------------------------------------------------------------
// K6: divide by du, computed analytically from the reference's degenerate
// degree loop (only indices heads[0],heads[2],rels[0],rels[2],tails[0],
// tails[2] can deviate from 1).
// ---------------------------------------------------------------------------
__global__ void k_div(float* __restrict__ out,
                      const int* __restrict__ heads,
                      const int* __restrict__ tails,
                      const int* __restrict__ rels, int total4) {
    int i = blockIdx.x * blockDim.x + threadIdx.x;
    if (i >= total4) return;
    int h0 = heads[0], h2 = heads[2];
    int t0 = tails[0], t2 = tails[2];
    int r0 = rels[0],  r2 = rels[2];
    int row = i >> 5;   // i / DIM4

    float du = 1.f;
    if (h0 != h2) du += (float)((row == h0) + (row == h2));
    if (r0 != r2) du += (float)((row == r0) + (row == r2));
    if (t0 != t2) du += (float)((row == t0) + (row == t2));

    float inv = 1.0f / du;   // exact for du in {1,2,4}; <=1ulp otherwise
    float4 v = reinterpret_cast<float4*>(out)[i];
    v.x *= inv; v.y *= inv; v.z *= inv; v.w *= inv;
    reinterpret_cast<float4*>(out)[i] = v;
}

// ---------------------------------------------------------------------------
// Launch
// ---------------------------------------------------------------------------
extern "C" void kernel_launch(void* const* d_in, const int* in_sizes, int n_in,
                              void* d_out, int out_size) {
    const float* x      = (const float*)d_in[0];
    const float* r      = (const float*)d_in[1];
    const float* gamma  = (const float*)d_in[2];
    const float* beta   = (const float*)d_in[3];
    const float* kern   = (const float*)d_in[4];
    const int* edges    = (const int*)d_in[5];
    const int* rels     = (const int*)d_in[6];

    int e = in_sizes[0] / DIM;           // 50000
    int rsc_total = in_sizes[1];         // n_rels * DIM
    int E = in_sizes[6];                 // 625000
    const int* heads = edges;
    const int* tails = edges + E;
    float* out = (float*)d_out;

    int total4 = e * DIM4;               // float4 count of [e, DIM]

    k_stats<<<NSTATB, DIM>>>(x, e);
    k_coef<<<1, DIM>>>(gamma, beta, kern, e);
    k_rsc<<<(rsc_total + 255) / 256, 256>>>(r, kern, rsc_total);
    k_norm<<<(total4 + 255) / 256, 256>>>(x, out, total4);
    k_edges<<<(E + 7) / 8, 256>>>(heads, tails, rels, out, E);
    k_div<<<(total4 + 255) / 256, 256>>>(out, heads, tails, rels, total4);
}